// round 14
// baseline (speedup 1.0000x reference)
#include <cuda_runtime.h>
#include <cuda_bf16.h>
#include <cstdint>

// KAT_Group rational activation: out = P5(z; a) / Q4(z; |b|), grouped along last dim.
//   x: (B, L, D) fp32, D = 2048, G = 8 groups of 256.
//
// FINAL (R9 config, measured best of 9 variants across R2-R13 sweep):
//   - flat launch, TPB=256, 4 front-batched 256-bit loads per thread
//   - loads:  ld.global.cs.v8.f32  (read-once, keep L2 clean)
//   - stores: st.global.v8.f32     (write-back; best measured store policy)
//   - guarded indexing (predication measured free; exact-fit variant raised
//     register pressure and regressed)
// Kernel sits at the LTS/HBM chip throughput cap (~7.3 TB/s combined
// dur-based) for a 1:1 read/write stream; occupancy/MLP/persistence all
// measured non-binding.

#ifndef KAT_D
#define KAT_D 2048
#endif

#define F8PT 4   // float8s per thread
#define TPB  256

struct __align__(32) f8 { float v[8]; };

__device__ __forceinline__ f8 ldg256_cs(const f8* p) {
    f8 r;
#if defined(__CUDA_ARCH__) && (__CUDA_ARCH__ >= 1000)
    asm volatile("ld.global.cs.v8.f32 {%0,%1,%2,%3,%4,%5,%6,%7}, [%8];"
                 : "=f"(r.v[0]), "=f"(r.v[1]), "=f"(r.v[2]), "=f"(r.v[3]),
                   "=f"(r.v[4]), "=f"(r.v[5]), "=f"(r.v[6]), "=f"(r.v[7])
                 : "l"(p));
#else
    const float4* p4 = reinterpret_cast<const float4*>(p);
    float4 lo = __ldcs(p4);
    float4 hi = __ldcs(p4 + 1);
    r.v[0] = lo.x; r.v[1] = lo.y; r.v[2] = lo.z; r.v[3] = lo.w;
    r.v[4] = hi.x; r.v[5] = hi.y; r.v[6] = hi.z; r.v[7] = hi.w;
#endif
    return r;
}

// Default (write-back) 256-bit store.
__device__ __forceinline__ void stg256_wb(f8* p, const f8& r) {
#if defined(__CUDA_ARCH__) && (__CUDA_ARCH__ >= 1000)
    asm volatile("st.global.v8.f32 [%0], {%1,%2,%3,%4,%5,%6,%7,%8};"
                 :: "l"(p),
                    "f"(r.v[0]), "f"(r.v[1]), "f"(r.v[2]), "f"(r.v[3]),
                    "f"(r.v[4]), "f"(r.v[5]), "f"(r.v[6]), "f"(r.v[7])
                 : "memory");
#else
    float4* p4 = reinterpret_cast<float4*>(p);
    p4[0] = make_float4(r.v[0], r.v[1], r.v[2], r.v[3]);
    p4[1] = make_float4(r.v[4], r.v[5], r.v[6], r.v[7]);
#endif
}

__global__ void __launch_bounds__(TPB)
kat_group_kernel(const f8* __restrict__ x8,
                 const float*  __restrict__ wn,    // 6 numerator coefs (uniform)
                 const float4* __restrict__ wd4,   // G x (b1..b4)
                 f8* __restrict__ out8,
                 int n8, int d8_mask, int dpg8_shift)
{
    const int base = blockIdx.x * (TPB * F8PT) + threadIdx.x;

    // front-batched 256-bit loads: 4 independent LDG in flight per thread
    f8  zv[F8PT];
    int idx[F8PT];
    bool ok[F8PT];
#pragma unroll
    for (int k = 0; k < F8PT; ++k) {
        idx[k] = base + k * TPB;
        ok[k]  = idx[k] < n8;
        if (ok[k]) zv[k] = ldg256_cs(&x8[idx[k]]);
    }

    // numerator coefs: uniform -> L1 broadcast
    const float a0 = __ldg(&wn[0]);
    const float a1 = __ldg(&wn[1]);
    const float a2 = __ldg(&wn[2]);
    const float a3 = __ldg(&wn[3]);
    const float a4 = __ldg(&wn[4]);
    const float a5 = __ldg(&wn[5]);

#pragma unroll
    for (int k = 0; k < F8PT; ++k) {
        if (!ok[k]) continue;

        const int g = (idx[k] & d8_mask) >> dpg8_shift;  // group uniform over the float8
        const float4 b = __ldg(&wd4[g]);
        const float b1 = fabsf(b.x);
        const float b2 = fabsf(b.y);
        const float b3 = fabsf(b.z);
        const float b4 = fabsf(b.w);

        f8 r;
#pragma unroll
        for (int e = 0; e < 8; ++e) {
            const float z = zv[k].v[e];
            float num = fmaf(a5, z, a4);
            num = fmaf(num, z, a3);
            num = fmaf(num, z, a2);
            num = fmaf(num, z, a1);
            num = fmaf(num, z, a0);
            float den = fmaf(b4, z, b3);
            den = fmaf(den, z, b2);
            den = fmaf(den, z, b1);
            den = fmaf(den, z, 1.0f);
            r.v[e] = __fdividef(num, den);
        }
        stg256_wb(&out8[idx[k]], r);
    }
}

extern "C" void kernel_launch(void* const* d_in, const int* in_sizes, int n_in,
                              void* d_out, int out_size)
{
    const f8*     x8  = (const f8*)    d_in[0];
    const float*  wn  = (const float*) d_in[1];
    const float4* wd4 = (const float4*)d_in[2];
    f8* out8 = (f8*)d_out;

    const int n8 = out_size / 8;

    int G = in_sizes[2] / 4;
    if (G <= 0) G = 8;
    const int d8   = KAT_D / 8;          // 256 float8s per row
    const int dpg8 = d8 / G;             // 32 float8s per group
    int shift = 0;
    while ((1 << shift) < dpg8) ++shift;

    const int per_block = TPB * F8PT;    // 1024 float8s per block
    const int blocks = (n8 + per_block - 1) / per_block;
    kat_group_kernel<<<blocks, TPB>>>(x8, wn, wd4, out8,
                                      n8, d8 - 1, shift);
}